// round 8
// baseline (speedup 1.0000x reference)
#include <cuda_runtime.h>
#include <cuda.h>          // CUtensorMap type (header-only use; symbol via runtime lookup)
#include <utility>
#include <cstddef>
#include <cstdint>

// Problem constants (fixed by the reference: N_COLS=16, ADD=3)
#define NC      16         // input columns
#define NTOT    696        // 16 + C(16,2)=120 + C(16,3)=560
#define NTOT4   174        // NTOT / 4
#define TPB     128        // threads per block == rows per tile
#define CCOLS   32         // output columns per full TMA chunk (21*32 + 24 = 696)
#define NFULL   21         // full 32-col chunks
#define LASTC   24         // final chunk columns
#define SPAN    128        // SW128 swizzle span = smem row pitch (bytes)
#define BUFB    (TPB * SPAN)   // 16 KB per buffer
#define NBUF    3          // triple buffer: 48 KB dynamic smem (default limit, no attr)

// ---------------------------------------------------------------------------
// Compile-time decode of output column g -> (i, j, k) subset indices.
// sel: 0 -> i, 1 -> j, 2 -> k.  Returns NC (=16) as "unused" sentinel.
__host__ __device__ constexpr int decode(int g, int sel) {
    if (g < NC) return sel == 0 ? g : NC;           // passthrough columns
    g -= NC;
    if (g < 120) {                                   // pairs, lexicographic
        int c = 0;
        for (int a = 0; a < NC; a++)
            for (int b = a + 1; b < NC; b++) {
                if (c == g) return sel == 0 ? a : (sel == 1 ? b : NC);
                c++;
            }
    } else {                                         // triples, lexicographic
        g -= 120;
        int c = 0;
        for (int a = 0; a < NC; a++)
            for (int b = a + 1; b < NC; b++)
                for (int d = b + 1; d < NC; d++) {
                    if (c == g) return sel == 0 ? a : (sel == 1 ? b : d);
                    c++;
                }
    }
    return NC;
}

// One output term; compile-time indices keep v[] in registers. NO register
// cap: ptxas caching pair products across chunks is what keeps the per-chunk
// compute phase short (R6 lesson: capping regs rematerializes serial FMUL
// chains and the barrier-paced chunk round stretches 2-3x).
template <int G>
__device__ __forceinline__ float term(const float (&v)[NC]) {
    constexpr int i = decode(G, 0);
    constexpr int j = decode(G, 1);
    constexpr int k = decode(G, 2);
    float r = v[i];
    if constexpr (j < NC) r = r * v[j];
    if constexpr (k < NC) r = r * v[k];
    return r;
}

__device__ __forceinline__ uint32_t smem_u32(const void* p) {
    uint32_t a;
    asm("{ .reg .u64 t; cvta.to.shared.u64 t, %1; cvt.u32.u64 %0, t; }" : "=r"(a) : "l"(p));
    return a;
}

// Thread tid writes its row's float4s for the chunk starting at column C0
// into the SW128-swizzled tile: row pitch 128 B, logical atom I lands at
// physical atom I^(tid&7) -> conflict-free STS.128 (per-I, atoms distinct
// across the 8-lane subphase).
template <int C0, int... I>
__device__ __forceinline__ void compute_chunk(const float (&v)[NC], char* buf, int tid,
                                              std::integer_sequence<int, I...>) {
    ((*reinterpret_cast<float4*>(buf + tid * SPAN + ((I ^ (tid & 7)) << 4)) =
          make_float4(term<C0 + 4 * I + 0>(v),
                      term<C0 + 4 * I + 1>(v),
                      term<C0 + 4 * I + 2>(v),
                      term<C0 + 4 * I + 3>(v))), ...);
}

// One pipelined chunk (index C, column base C*CCOLS, NF4 float4s per row):
// reclaim buffer (allow 2 outstanding TMA smem-reads) -> compute -> fence ->
// barrier -> single-thread TMA 2D store + commit.
template <int C, int NF4>
__device__ __forceinline__ void do_chunk(const float (&v)[NC], char* sbase, int tid,
                                         const CUtensorMap* pmap, int row0) {
    char* buf = sbase + (C % NBUF) * BUFB;
    if constexpr (C >= NBUF) {
        if (tid == 0)
            asm volatile("cp.async.bulk.wait_group.read 2;" ::: "memory");
        __syncthreads();
    }
    compute_chunk<C * CCOLS>(v, buf, tid, std::make_integer_sequence<int, NF4>{});
    asm volatile("fence.proxy.async.shared::cta;" ::: "memory");
    __syncthreads();
    if (tid == 0) {
        uint32_t saddr = smem_u32(buf);
        asm volatile(
            "cp.async.bulk.tensor.2d.global.shared::cta.tile.bulk_group [%0, {%1, %2}], [%3];"
            :: "l"(pmap), "r"(C * CCOLS), "r"(row0), "r"(saddr) : "memory");
        asm volatile("cp.async.bulk.commit_group;" ::: "memory");
    }
}

template <int... Cs>
__device__ __forceinline__ void do_full_chunks(const float (&v)[NC], char* sbase, int tid,
                                               const CUtensorMap* pmap, int row0,
                                               std::integer_sequence<int, Cs...>) {
    (do_chunk<Cs, CCOLS / 4>(v, sbase, tid, pmap, row0), ...);
}

__global__ void __launch_bounds__(TPB)
algebraic_tma_kernel(const float* __restrict__ x,
                     const __grid_constant__ CUtensorMap tmap_a,   // box [32,128]
                     const __grid_constant__ CUtensorMap tmap_b) { // box [24,128]
    extern __shared__ char sbuf[];            // 3 x 16 KB, dynamic -> span-aligned base

    const int tid  = threadIdx.x;
    const int row0 = blockIdx.x * TPB;

    float v[NC];
    {
        const float4* xp = reinterpret_cast<const float4*>(x) +
                           ((size_t)row0 + tid) * (NC / 4);
        float4 a = xp[0], b = xp[1], c = xp[2], d = xp[3];
        v[0]  = a.x; v[1]  = a.y; v[2]  = a.z; v[3]  = a.w;
        v[4]  = b.x; v[5]  = b.y; v[6]  = b.z; v[7]  = b.w;
        v[8]  = c.x; v[9]  = c.y; v[10] = c.z; v[11] = c.w;
        v[12] = d.x; v[13] = d.y; v[14] = d.z; v[15] = d.w;
    }

    // 21 full 32-col chunks through tmap_a ...
    do_full_chunks(v, sbuf, tid, &tmap_a, row0, std::make_integer_sequence<int, NFULL>{});
    // ... and the final 24-col chunk (columns 672..695) through tmap_b.
    do_chunk<NFULL, LASTC / 4>(v, sbuf, tid, &tmap_b, row0);

    if (tid == 0)
        asm volatile("cp.async.bulk.wait_group 0;" ::: "memory");
}

// ---------------------------------------------------------------------------
// Fallback (only if tensormap creation is unavailable): direct strided stores.
template <int... I>
__device__ __forceinline__ void store_all(const float (&v)[NC], float4* __restrict__ o,
                                          std::integer_sequence<int, I...>) {
    ((o[I] = make_float4(term<4 * I + 0>(v), term<4 * I + 1>(v),
                         term<4 * I + 2>(v), term<4 * I + 3>(v))), ...);
}

__global__ void __launch_bounds__(TPB)
algebraic_fallback_kernel(const float* __restrict__ x, float4* __restrict__ out4) {
    const size_t row = (size_t)blockIdx.x * TPB + threadIdx.x;
    float v[NC];
    const float4* xp = reinterpret_cast<const float4*>(x) + row * (NC / 4);
    float4 a = xp[0], b = xp[1], c = xp[2], d = xp[3];
    v[0]  = a.x; v[1]  = a.y; v[2]  = a.z; v[3]  = a.w;
    v[4]  = b.x; v[5]  = b.y; v[6]  = b.z; v[7]  = b.w;
    v[8]  = c.x; v[9]  = c.y; v[10] = c.z; v[11] = c.w;
    v[12] = d.x; v[13] = d.y; v[14] = d.z; v[15] = d.w;
    store_all(v, out4 + row * NTOT4, std::make_integer_sequence<int, NTOT4>{});
}

// ---------------------------------------------------------------------------
extern "C" void kernel_launch(void* const* d_in, const int* in_sizes, int n_in,
                              void* d_out, int out_size) {
    const float* x  = (const float*)d_in[0];
    const int nrows = in_sizes[0] / NC;            // 262144 (multiple of 128)
    const int blocks = nrows / TPB;                // 2048

    // Resolve cuTensorMapEncodeTiled through the runtime (no -lcuda link dep).
    typedef CUresult (*EncodeFn)(CUtensorMap*, CUtensorMapDataType, cuuint32_t, void*,
                                 const cuuint64_t*, const cuuint64_t*, const cuuint32_t*,
                                 const cuuint32_t*, CUtensorMapInterleave, CUtensorMapSwizzle,
                                 CUtensorMapL2promotion, CUtensorMapFloatOOBfill);
    EncodeFn encode = nullptr;
    {
        void* p = nullptr;
        cudaDriverEntryPointQueryResult st;
        if (cudaGetDriverEntryPointByVersion("cuTensorMapEncodeTiled", &p, 12000,
                                             cudaEnableDefault, &st) == cudaSuccess &&
            st == cudaDriverEntryPointSuccess)
            encode = (EncodeFn)p;
    }

    alignas(64) CUtensorMap tmap_a, tmap_b;
    bool tma_ok = false;
    if (encode) {
        cuuint64_t dims[2]    = {(cuuint64_t)NTOT, (cuuint64_t)nrows};
        cuuint64_t strides[1] = {(cuuint64_t)NTOT * sizeof(float)};   // 2784 B, 16B-multiple
        cuuint32_t estr[2]    = {1, 1};
        cuuint32_t box_a[2]   = {CCOLS, TPB};                         // 128 B x 128 rows
        cuuint32_t box_b[2]   = {LASTC, TPB};                         //  96 B x 128 rows
        bool oka = (encode(&tmap_a, CU_TENSOR_MAP_DATA_TYPE_FLOAT32, 2, d_out,
                           dims, strides, box_a, estr,
                           CU_TENSOR_MAP_INTERLEAVE_NONE, CU_TENSOR_MAP_SWIZZLE_128B,
                           CU_TENSOR_MAP_L2_PROMOTION_L2_128B,
                           CU_TENSOR_MAP_FLOAT_OOB_FILL_NONE) == CUDA_SUCCESS);
        bool okb = (encode(&tmap_b, CU_TENSOR_MAP_DATA_TYPE_FLOAT32, 2, d_out,
                           dims, strides, box_b, estr,
                           CU_TENSOR_MAP_INTERLEAVE_NONE, CU_TENSOR_MAP_SWIZZLE_128B,
                           CU_TENSOR_MAP_L2_PROMOTION_L2_128B,
                           CU_TENSOR_MAP_FLOAT_OOB_FILL_NONE) == CUDA_SUCCESS);
        tma_ok = oka && okb;
    }

    if (tma_ok) {
        algebraic_tma_kernel<<<blocks, TPB, NBUF * BUFB>>>(x, tmap_a, tmap_b);
    } else {
        algebraic_fallback_kernel<<<blocks, TPB>>>(x, (float4*)d_out);
    }
}

// round 9
// speedup vs baseline: 1.0008x; 1.0008x over previous
#include <cuda_runtime.h>
#include <cuda.h>          // CUtensorMap type (header-only use; symbol via runtime lookup)
#include <utility>
#include <cstddef>
#include <cstdint>

// Problem constants (fixed by the reference: N_COLS=16, ADD=3)
#define NC      16         // input columns
#define NTOT    696        // 16 + C(16,2)=120 + C(16,3)=560
#define NTOT4   174        // NTOT / 4
#define TPB     128        // threads per block == rows per tile
#define CCOLS   32         // output columns per full TMA chunk (21*32 + 24 = 696)
#define NFULL   21         // full 32-col chunks
#define LASTC   24         // final chunk columns
#define SPAN    128        // SW128 swizzle span = smem row pitch (bytes)
#define BUFB    (TPB * SPAN)   // 16 KB per buffer
#define NBUF    3          // triple buffer: 48 KB dynamic smem (default limit, no attr)

// ---------------------------------------------------------------------------
// Compile-time decode of output column g -> (i, j, k) subset indices.
// sel: 0 -> i, 1 -> j, 2 -> k.  Returns NC (=16) as "unused" sentinel.
__host__ __device__ constexpr int decode(int g, int sel) {
    if (g < NC) return sel == 0 ? g : NC;           // passthrough columns
    g -= NC;
    if (g < 120) {                                   // pairs, lexicographic
        int c = 0;
        for (int a = 0; a < NC; a++)
            for (int b = a + 1; b < NC; b++) {
                if (c == g) return sel == 0 ? a : (sel == 1 ? b : NC);
                c++;
            }
    } else {                                         // triples, lexicographic
        g -= 120;
        int c = 0;
        for (int a = 0; a < NC; a++)
            for (int b = a + 1; b < NC; b++)
                for (int d = b + 1; d < NC; d++) {
                    if (c == g) return sel == 0 ? a : (sel == 1 ? b : d);
                    c++;
                }
    }
    return NC;
}

// One output term; compile-time indices keep v[] in registers. NO register
// cap: ptxas caching pair products across chunks is what keeps the per-chunk
// compute phase short (R6 lesson: capping regs rematerializes serial FMUL
// chains and the barrier-paced chunk round stretches 2-3x).
template <int G>
__device__ __forceinline__ float term(const float (&v)[NC]) {
    constexpr int i = decode(G, 0);
    constexpr int j = decode(G, 1);
    constexpr int k = decode(G, 2);
    float r = v[i];
    if constexpr (j < NC) r = r * v[j];
    if constexpr (k < NC) r = r * v[k];
    return r;
}

__device__ __forceinline__ uint32_t smem_u32(const void* p) {
    uint32_t a;
    asm("{ .reg .u64 t; cvta.to.shared.u64 t, %1; cvt.u32.u64 %0, t; }" : "=r"(a) : "l"(p));
    return a;
}

// Thread tid writes its row's float4s for the chunk starting at column C0
// into the SW128-swizzled tile: row pitch 128 B, logical atom I lands at
// physical atom I^(tid&7) -> conflict-free STS.128 (per-I, atoms distinct
// across the 8-lane subphase).
template <int C0, int... I>
__device__ __forceinline__ void compute_chunk(const float (&v)[NC], char* buf, int tid,
                                              std::integer_sequence<int, I...>) {
    ((*reinterpret_cast<float4*>(buf + tid * SPAN + ((I ^ (tid & 7)) << 4)) =
          make_float4(term<C0 + 4 * I + 0>(v),
                      term<C0 + 4 * I + 1>(v),
                      term<C0 + 4 * I + 2>(v),
                      term<C0 + 4 * I + 3>(v))), ...);
}

// One pipelined chunk (index C, column base C*CCOLS, NF4 float4s per row):
// reclaim buffer (allow 2 outstanding TMA smem-reads) -> compute -> fence ->
// barrier -> single-thread TMA 2D store + commit.
template <int C, int NF4>
__device__ __forceinline__ void do_chunk(const float (&v)[NC], char* sbase, int tid,
                                         const CUtensorMap* pmap, int row0) {
    char* buf = sbase + (C % NBUF) * BUFB;
    if constexpr (C >= NBUF) {
        if (tid == 0)
            asm volatile("cp.async.bulk.wait_group.read 2;" ::: "memory");
        __syncthreads();
    }
    compute_chunk<C * CCOLS>(v, buf, tid, std::make_integer_sequence<int, NF4>{});
    asm volatile("fence.proxy.async.shared::cta;" ::: "memory");
    __syncthreads();
    if (tid == 0) {
        uint32_t saddr = smem_u32(buf);
        asm volatile(
            "cp.async.bulk.tensor.2d.global.shared::cta.tile.bulk_group [%0, {%1, %2}], [%3];"
            :: "l"(pmap), "r"(C * CCOLS), "r"(row0), "r"(saddr) : "memory");
        asm volatile("cp.async.bulk.commit_group;" ::: "memory");
    }
}

template <int... Cs>
__device__ __forceinline__ void do_full_chunks(const float (&v)[NC], char* sbase, int tid,
                                               const CUtensorMap* pmap, int row0,
                                               std::integer_sequence<int, Cs...>) {
    (do_chunk<Cs, CCOLS / 4>(v, sbase, tid, pmap, row0), ...);
}

__global__ void __launch_bounds__(TPB)
algebraic_tma_kernel(const float* __restrict__ x,
                     const __grid_constant__ CUtensorMap tmap_a,   // box [32,128]
                     const __grid_constant__ CUtensorMap tmap_b) { // box [24,128]
    extern __shared__ char sbuf[];            // 3 x 16 KB, dynamic -> span-aligned base

    const int tid  = threadIdx.x;
    const int row0 = blockIdx.x * TPB;

    float v[NC];
    {
        const float4* xp = reinterpret_cast<const float4*>(x) +
                           ((size_t)row0 + tid) * (NC / 4);
        float4 a = xp[0], b = xp[1], c = xp[2], d = xp[3];
        v[0]  = a.x; v[1]  = a.y; v[2]  = a.z; v[3]  = a.w;
        v[4]  = b.x; v[5]  = b.y; v[6]  = b.z; v[7]  = b.w;
        v[8]  = c.x; v[9]  = c.y; v[10] = c.z; v[11] = c.w;
        v[12] = d.x; v[13] = d.y; v[14] = d.z; v[15] = d.w;
    }

    // 21 full 32-col chunks through tmap_a ...
    do_full_chunks(v, sbuf, tid, &tmap_a, row0, std::make_integer_sequence<int, NFULL>{});
    // ... and the final 24-col chunk (columns 672..695) through tmap_b.
    do_chunk<NFULL, LASTC / 4>(v, sbuf, tid, &tmap_b, row0);

    if (tid == 0)
        asm volatile("cp.async.bulk.wait_group 0;" ::: "memory");
}

// ---------------------------------------------------------------------------
// Fallback (only if tensormap creation is unavailable): direct strided stores.
template <int... I>
__device__ __forceinline__ void store_all(const float (&v)[NC], float4* __restrict__ o,
                                          std::integer_sequence<int, I...>) {
    ((o[I] = make_float4(term<4 * I + 0>(v), term<4 * I + 1>(v),
                         term<4 * I + 2>(v), term<4 * I + 3>(v))), ...);
}

__global__ void __launch_bounds__(TPB)
algebraic_fallback_kernel(const float* __restrict__ x, float4* __restrict__ out4) {
    const size_t row = (size_t)blockIdx.x * TPB + threadIdx.x;
    float v[NC];
    const float4* xp = reinterpret_cast<const float4*>(x) + row * (NC / 4);
    float4 a = xp[0], b = xp[1], c = xp[2], d = xp[3];
    v[0]  = a.x; v[1]  = a.y; v[2]  = a.z; v[3]  = a.w;
    v[4]  = b.x; v[5]  = b.y; v[6]  = b.z; v[7]  = b.w;
    v[8]  = c.x; v[9]  = c.y; v[10] = c.z; v[11] = c.w;
    v[12] = d.x; v[13] = d.y; v[14] = d.z; v[15] = d.w;
    store_all(v, out4 + row * NTOT4, std::make_integer_sequence<int, NTOT4>{});
}

// ---------------------------------------------------------------------------
extern "C" void kernel_launch(void* const* d_in, const int* in_sizes, int n_in,
                              void* d_out, int out_size) {
    const float* x  = (const float*)d_in[0];
    const int nrows = in_sizes[0] / NC;            // 262144 (multiple of 128)
    const int blocks = nrows / TPB;                // 2048

    // Resolve cuTensorMapEncodeTiled through the runtime (no -lcuda link dep).
    typedef CUresult (*EncodeFn)(CUtensorMap*, CUtensorMapDataType, cuuint32_t, void*,
                                 const cuuint64_t*, const cuuint64_t*, const cuuint32_t*,
                                 const cuuint32_t*, CUtensorMapInterleave, CUtensorMapSwizzle,
                                 CUtensorMapL2promotion, CUtensorMapFloatOOBfill);
    EncodeFn encode = nullptr;
    {
        void* p = nullptr;
        cudaDriverEntryPointQueryResult st;
        if (cudaGetDriverEntryPointByVersion("cuTensorMapEncodeTiled", &p, 12000,
                                             cudaEnableDefault, &st) == cudaSuccess &&
            st == cudaDriverEntryPointSuccess)
            encode = (EncodeFn)p;
    }

    alignas(64) CUtensorMap tmap_a, tmap_b;
    bool tma_ok = false;
    if (encode) {
        cuuint64_t dims[2]    = {(cuuint64_t)NTOT, (cuuint64_t)nrows};
        cuuint64_t strides[1] = {(cuuint64_t)NTOT * sizeof(float)};   // 2784 B, 16B-multiple
        cuuint32_t estr[2]    = {1, 1};
        cuuint32_t box_a[2]   = {CCOLS, TPB};                         // 128 B x 128 rows
        cuuint32_t box_b[2]   = {LASTC, TPB};                         //  96 B x 128 rows
        bool oka = (encode(&tmap_a, CU_TENSOR_MAP_DATA_TYPE_FLOAT32, 2, d_out,
                           dims, strides, box_a, estr,
                           CU_TENSOR_MAP_INTERLEAVE_NONE, CU_TENSOR_MAP_SWIZZLE_128B,
                           CU_TENSOR_MAP_L2_PROMOTION_L2_128B,
                           CU_TENSOR_MAP_FLOAT_OOB_FILL_NONE) == CUDA_SUCCESS);
        bool okb = (encode(&tmap_b, CU_TENSOR_MAP_DATA_TYPE_FLOAT32, 2, d_out,
                           dims, strides, box_b, estr,
                           CU_TENSOR_MAP_INTERLEAVE_NONE, CU_TENSOR_MAP_SWIZZLE_128B,
                           CU_TENSOR_MAP_L2_PROMOTION_L2_128B,
                           CU_TENSOR_MAP_FLOAT_OOB_FILL_NONE) == CUDA_SUCCESS);
        tma_ok = oka && okb;
    }

    if (tma_ok) {
        algebraic_tma_kernel<<<blocks, TPB, NBUF * BUFB>>>(x, tmap_a, tmap_b);
    } else {
        algebraic_fallback_kernel<<<blocks, TPB>>>(x, (float4*)d_out);
    }
}

// round 10
// speedup vs baseline: 1.0206x; 1.0198x over previous
#include <cuda_runtime.h>
#include <cuda.h>          // CUtensorMap type (header-only use; symbol via runtime lookup)
#include <utility>
#include <cstddef>
#include <cstdint>

// Problem constants (fixed by the reference: N_COLS=16, ADD=3)
#define NC      16         // input columns
#define NTOT    696        // 16 + C(16,2)=120 + C(16,3)=560
#define NTOT4   174        // NTOT / 4
#define TPB     128        // threads per block == rows per tile
#define CCOLS   32         // output columns per full TMA chunk (21*32 + 24 = 696)
#define NFULL   21         // full 32-col chunks
#define LASTC   24         // final chunk columns
#define SPAN    128        // SW128 swizzle span = smem row pitch (bytes)
#define BUFB    (TPB * SPAN)   // 16 KB per buffer
#define NBUF    4          // quad buffer: 64 KB dynamic smem (opt-in attribute)
                           // 3 blocks/SM: regs 155*128*3=59.5K<=64K, smem 192KB<=228KB

// ---------------------------------------------------------------------------
// Compile-time decode of output column g -> (i, j, k) subset indices.
// sel: 0 -> i, 1 -> j, 2 -> k.  Returns NC (=16) as "unused" sentinel.
__host__ __device__ constexpr int decode(int g, int sel) {
    if (g < NC) return sel == 0 ? g : NC;           // passthrough columns
    g -= NC;
    if (g < 120) {                                   // pairs, lexicographic
        int c = 0;
        for (int a = 0; a < NC; a++)
            for (int b = a + 1; b < NC; b++) {
                if (c == g) return sel == 0 ? a : (sel == 1 ? b : NC);
                c++;
            }
    } else {                                         // triples, lexicographic
        g -= 120;
        int c = 0;
        for (int a = 0; a < NC; a++)
            for (int b = a + 1; b < NC; b++)
                for (int d = b + 1; d < NC; d++) {
                    if (c == g) return sel == 0 ? a : (sel == 1 ? b : d);
                    c++;
                }
    }
    return NC;
}

// One output term; compile-time indices keep v[] in registers. NO register
// cap: ptxas caching pair products across chunks keeps the per-chunk compute
// phase short (R6 lesson: capping regs rematerializes serial FMUL chains and
// the barrier-paced chunk round stretches 2-3x).
template <int G>
__device__ __forceinline__ float term(const float (&v)[NC]) {
    constexpr int i = decode(G, 0);
    constexpr int j = decode(G, 1);
    constexpr int k = decode(G, 2);
    float r = v[i];
    if constexpr (j < NC) r = r * v[j];
    if constexpr (k < NC) r = r * v[k];
    return r;
}

__device__ __forceinline__ uint32_t smem_u32(const void* p) {
    uint32_t a;
    asm("{ .reg .u64 t; cvta.to.shared.u64 t, %1; cvt.u32.u64 %0, t; }" : "=r"(a) : "l"(p));
    return a;
}

// Thread tid writes its row's float4s for the chunk starting at column C0
// into the SW128-swizzled tile: row pitch 128 B, logical atom I lands at
// physical atom I^(tid&7) -> conflict-free STS.128 (per-I, atoms distinct
// across the 8-lane subphase).
template <int C0, int... I>
__device__ __forceinline__ void compute_chunk(const float (&v)[NC], char* buf, int tid,
                                              std::integer_sequence<int, I...>) {
    ((*reinterpret_cast<float4*>(buf + tid * SPAN + ((I ^ (tid & 7)) << 4)) =
          make_float4(term<C0 + 4 * I + 0>(v),
                      term<C0 + 4 * I + 1>(v),
                      term<C0 + 4 * I + 2>(v),
                      term<C0 + 4 * I + 3>(v))), ...);
}

// One pipelined chunk (index C, column base C*CCOLS, NF4 float4s per row):
// reclaim buffer (allow NBUF-1 outstanding TMA smem-reads) -> compute ->
// async-proxy fence -> barrier -> single-thread TMA 2D store + commit.
template <int C, int NF4>
__device__ __forceinline__ void do_chunk(const float (&v)[NC], char* sbase, int tid,
                                         const CUtensorMap* pmap, int row0) {
    char* buf = sbase + (C % NBUF) * BUFB;
    if constexpr (C >= NBUF) {
        if (tid == 0)
            asm volatile("cp.async.bulk.wait_group.read 3;" ::: "memory");
        __syncthreads();
    }
    compute_chunk<C * CCOLS>(v, buf, tid, std::make_integer_sequence<int, NF4>{});
    asm volatile("fence.proxy.async.shared::cta;" ::: "memory");
    __syncthreads();
    if (tid == 0) {
        uint32_t saddr = smem_u32(buf);
        asm volatile(
            "cp.async.bulk.tensor.2d.global.shared::cta.tile.bulk_group [%0, {%1, %2}], [%3];"
            :: "l"(pmap), "r"(C * CCOLS), "r"(row0), "r"(saddr) : "memory");
        asm volatile("cp.async.bulk.commit_group;" ::: "memory");
    }
}

template <int... Cs>
__device__ __forceinline__ void do_full_chunks(const float (&v)[NC], char* sbase, int tid,
                                               const CUtensorMap* pmap, int row0,
                                               std::integer_sequence<int, Cs...>) {
    (do_chunk<Cs, CCOLS / 4>(v, sbase, tid, pmap, row0), ...);
}

__global__ void __launch_bounds__(TPB)
algebraic_tma_kernel(const float* __restrict__ x,
                     const __grid_constant__ CUtensorMap tmap_a,   // box [32,128]
                     const __grid_constant__ CUtensorMap tmap_b) { // box [24,128]
    extern __shared__ char sbuf[];            // 4 x 16 KB, dynamic -> span-aligned base

    const int tid  = threadIdx.x;
    const int row0 = blockIdx.x * TPB;

    float v[NC];
    {
        const float4* xp = reinterpret_cast<const float4*>(x) +
                           ((size_t)row0 + tid) * (NC / 4);
        float4 a = xp[0], b = xp[1], c = xp[2], d = xp[3];
        v[0]  = a.x; v[1]  = a.y; v[2]  = a.z; v[3]  = a.w;
        v[4]  = b.x; v[5]  = b.y; v[6]  = b.z; v[7]  = b.w;
        v[8]  = c.x; v[9]  = c.y; v[10] = c.z; v[11] = c.w;
        v[12] = d.x; v[13] = d.y; v[14] = d.z; v[15] = d.w;
    }

    // 21 full 32-col chunks through tmap_a ...
    do_full_chunks(v, sbuf, tid, &tmap_a, row0, std::make_integer_sequence<int, NFULL>{});
    // ... and the final 24-col chunk (columns 672..695) through tmap_b.
    do_chunk<NFULL, LASTC / 4>(v, sbuf, tid, &tmap_b, row0);

    if (tid == 0)
        asm volatile("cp.async.bulk.wait_group 0;" ::: "memory");
}

// ---------------------------------------------------------------------------
// Fallback (only if tensormap creation is unavailable): direct strided stores.
template <int... I>
__device__ __forceinline__ void store_all(const float (&v)[NC], float4* __restrict__ o,
                                          std::integer_sequence<int, I...>) {
    ((o[I] = make_float4(term<4 * I + 0>(v), term<4 * I + 1>(v),
                         term<4 * I + 2>(v), term<4 * I + 3>(v))), ...);
}

__global__ void __launch_bounds__(TPB)
algebraic_fallback_kernel(const float* __restrict__ x, float4* __restrict__ out4) {
    const size_t row = (size_t)blockIdx.x * TPB + threadIdx.x;
    float v[NC];
    const float4* xp = reinterpret_cast<const float4*>(x) + row * (NC / 4);
    float4 a = xp[0], b = xp[1], c = xp[2], d = xp[3];
    v[0]  = a.x; v[1]  = a.y; v[2]  = a.z; v[3]  = a.w;
    v[4]  = b.x; v[5]  = b.y; v[6]  = b.z; v[7]  = b.w;
    v[8]  = c.x; v[9]  = c.y; v[10] = c.z; v[11] = c.w;
    v[12] = d.x; v[13] = d.y; v[14] = d.z; v[15] = d.w;
    store_all(v, out4 + row * NTOT4, std::make_integer_sequence<int, NTOT4>{});
}

// ---------------------------------------------------------------------------
extern "C" void kernel_launch(void* const* d_in, const int* in_sizes, int n_in,
                              void* d_out, int out_size) {
    const float* x  = (const float*)d_in[0];
    const int nrows = in_sizes[0] / NC;            // 262144 (multiple of 128)
    const int blocks = nrows / TPB;                // 2048

    // Resolve cuTensorMapEncodeTiled through the runtime (no -lcuda link dep).
    typedef CUresult (*EncodeFn)(CUtensorMap*, CUtensorMapDataType, cuuint32_t, void*,
                                 const cuuint64_t*, const cuuint64_t*, const cuuint32_t*,
                                 const cuuint32_t*, CUtensorMapInterleave, CUtensorMapSwizzle,
                                 CUtensorMapL2promotion, CUtensorMapFloatOOBfill);
    EncodeFn encode = nullptr;
    {
        void* p = nullptr;
        cudaDriverEntryPointQueryResult st;
        if (cudaGetDriverEntryPointByVersion("cuTensorMapEncodeTiled", &p, 12000,
                                             cudaEnableDefault, &st) == cudaSuccess &&
            st == cudaDriverEntryPointSuccess)
            encode = (EncodeFn)p;
    }

    alignas(64) CUtensorMap tmap_a, tmap_b;
    bool tma_ok = false;
    if (encode) {
        cuuint64_t dims[2]    = {(cuuint64_t)NTOT, (cuuint64_t)nrows};
        cuuint64_t strides[1] = {(cuuint64_t)NTOT * sizeof(float)};   // 2784 B, 16B-multiple
        cuuint32_t estr[2]    = {1, 1};
        cuuint32_t box_a[2]   = {CCOLS, TPB};                         // 128 B x 128 rows
        cuuint32_t box_b[2]   = {LASTC, TPB};                         //  96 B x 128 rows
        bool oka = (encode(&tmap_a, CU_TENSOR_MAP_DATA_TYPE_FLOAT32, 2, d_out,
                           dims, strides, box_a, estr,
                           CU_TENSOR_MAP_INTERLEAVE_NONE, CU_TENSOR_MAP_SWIZZLE_128B,
                           CU_TENSOR_MAP_L2_PROMOTION_L2_128B,
                           CU_TENSOR_MAP_FLOAT_OOB_FILL_NONE) == CUDA_SUCCESS);
        bool okb = (encode(&tmap_b, CU_TENSOR_MAP_DATA_TYPE_FLOAT32, 2, d_out,
                           dims, strides, box_b, estr,
                           CU_TENSOR_MAP_INTERLEAVE_NONE, CU_TENSOR_MAP_SWIZZLE_128B,
                           CU_TENSOR_MAP_L2_PROMOTION_L2_128B,
                           CU_TENSOR_MAP_FLOAT_OOB_FILL_NONE) == CUDA_SUCCESS);
        tma_ok = oka && okb;
    }

    if (tma_ok) {
        // Opt into 64 KB dynamic smem (host state change, not an allocation).
        static bool attr_done = false;
        bool attr_ok = attr_done;
        if (!attr_ok) {
            attr_ok = (cudaFuncSetAttribute(algebraic_tma_kernel,
                                            cudaFuncAttributeMaxDynamicSharedMemorySize,
                                            NBUF * BUFB) == cudaSuccess);
            attr_done = attr_ok;
        }
        if (attr_ok) {
            algebraic_tma_kernel<<<blocks, TPB, NBUF * BUFB>>>(x, tmap_a, tmap_b);
            return;
        }
    }
    algebraic_fallback_kernel<<<blocks, TPB>>>(x, (float4*)d_out);
}